// round 10
// baseline (speedup 1.0000x reference)
#include <cuda_runtime.h>
#include <cstdint>

#define MAXN 100000
#define MAXE 800000
#define BN_EPS 1e-5f

typedef unsigned long long ull;

// ---------------- scratch ----------------------------------------------------
__device__ int   g_cnt[MAXN];
__device__ int   g_start[MAXN];
__device__ int   g_cursor[MAXN];
__device__ int   g_csr[MAXE];
__device__ int   g_bsum[128];
__device__ float g_dis[MAXN];            // rsqrt(deg+1)
__device__ float g_h1s[MAXN * 128];      // (x@W1)*dis
__device__ float g_z1[MAXN * 128];       // relu(bn(agg1))
__device__ float g_h2s[MAXN * 64];       // (z1@W2)*dis
__device__ float2 g_h3s[MAXN];           // (z2@W3)*dis
__device__ float g_scale1[128], g_shift1[128];
__device__ float g_scale2[64],  g_shift2[64];

// ---------------- f32x2 helpers ----------------------------------------------
__device__ __forceinline__ ull ffma2(ull a, ull b, ull c) {
    ull d; asm("fma.rn.f32x2 %0, %1, %2, %3;" : "=l"(d) : "l"(a), "l"(b), "l"(c));
    return d;
}
__device__ __forceinline__ ull pack2(float x, float y) {
    ull d; asm("mov.b64 %0, {%1,%2};" : "=l"(d) : "f"(x), "f"(y)); return d;
}
__device__ __forceinline__ float2 unpack2(ull v) {
    float2 r; asm("mov.b64 {%0,%1}, %2;" : "=f"(r.x), "=f"(r.y) : "l"(v)); return r;
}
__device__ __forceinline__ void add4(float4& a, const float4& v) {
    a.x += v.x; a.y += v.y; a.z += v.z; a.w += v.w;
}

// ---------------- k1: prep BN params + zero cnt --------------------------------
__global__ void prep_zero_kernel(const float* __restrict__ b1, const float* __restrict__ g1,
                                 const float* __restrict__ be1, const float* __restrict__ m1,
                                 const float* __restrict__ v1,
                                 const float* __restrict__ b2, const float* __restrict__ g2,
                                 const float* __restrict__ be2, const float* __restrict__ m2,
                                 const float* __restrict__ v2, int N) {
    int i = blockIdx.x * blockDim.x + threadIdx.x;
    if (i < N) g_cnt[i] = 0;
    if (blockIdx.x == 0) {
        int t = threadIdx.x;
        if (t < 128) {
            float s = g1[t] * rsqrtf(v1[t] + BN_EPS);
            g_scale1[t] = s;
            g_shift1[t] = fmaf(b1[t] - m1[t], s, be1[t]);
        }
        if (t < 64) {
            float s = g2[t] * rsqrtf(v2[t] + BN_EPS);
            g_scale2[t] = s;
            g_shift2[t] = fmaf(b2[t] - m2[t], s, be2[t]);
        }
    }
}

// ---------------- k2: hist ------------------------------------------------------
__global__ void hist_kernel(const int* __restrict__ ei, int E) {
    int e = blockIdx.x * blockDim.x + threadIdx.x;
    if (e < E) atomicAdd(&g_cnt[ei[E + e]], 1);
}

// ---------------- k3: per-block sums + dis --------------------------------------
__global__ void scan_part_kernel(int N) {
    __shared__ int sh[1024];
    int i = blockIdx.x * 1024 + threadIdx.x;
    int c = (i < N) ? g_cnt[i] : 0;
    if (i < N) g_dis[i] = rsqrtf((float)c + 1.0f);
    sh[threadIdx.x] = c; __syncthreads();
    for (int s = 512; s > 0; s >>= 1) {
        if (threadIdx.x < s) sh[threadIdx.x] += sh[threadIdx.x + s];
        __syncthreads();
    }
    if (threadIdx.x == 0) g_bsum[blockIdx.x] = sh[0];
}

// ---------------- k4 (PROFILED SLOT): persistent GEMM1 h1s = (x@W1)*dis ---------
// grid 592 (4/SM, 48KB); activations stored plain (broadcast LDS.64 + reg dup).
// thread = 8 rows x 4 cols.
extern __shared__ char smem_raw[];
__global__ __launch_bounds__(256) void gemm1_kernel(const float* __restrict__ x,
                                                    const float* __restrict__ W,
                                                    int N, int ntiles) {
    float* Ws = (float*)smem_raw;                              // [64][128] = 32KB
    float* xs = (float*)(smem_raw + 32768);                    // [64][64]  = 16KB
    float2 (*xs2)[32] = (float2(*)[32])xs;
    const int tid = threadIdx.x;
    for (int i = tid; i < 64 * 128; i += 256) Ws[i] = W[i];
    const int lane = tid & 31;   // cols lane*4..+3
    const int w    = tid >> 5;   // rows w*8..+7
    for (int tile = blockIdx.x; tile < ntiles; tile += gridDim.x) {
        const int base = tile * 64;
        __syncthreads();   // orders W-store (first iter) / prev compute vs tile load
        for (int i = tid; i < 1024; i += 256) {      // 64 rows x 16 float4
            int r = i >> 4, k4 = i & 15;
            int gr = base + r;
            float4 v = make_float4(0.f, 0.f, 0.f, 0.f);
            if (gr < N) v = *(const float4*)&x[(size_t)gr * 64 + k4 * 4];
            *(float4*)&xs[r * 64 + k4 * 4] = v;
        }
        __syncthreads();
        ull acc[8][2];
        #pragma unroll
        for (int r = 0; r < 8; r++) { acc[r][0] = 0ull; acc[r][1] = 0ull; }
        #pragma unroll 4
        for (int kk = 0; kk < 32; kk++) {
            ulonglong2 wv0 = *(const ulonglong2*)&Ws[(2 * kk + 0) * 128 + lane * 4];
            ulonglong2 wv1 = *(const ulonglong2*)&Ws[(2 * kk + 1) * 128 + lane * 4];
            #pragma unroll
            for (int r = 0; r < 8; r++) {
                float2 d = xs2[w * 8 + r][kk];
                ull dx = pack2(d.x, d.x);
                ull dy = pack2(d.y, d.y);
                acc[r][0] = ffma2(dx, wv0.x, acc[r][0]);
                acc[r][1] = ffma2(dx, wv0.y, acc[r][1]);
                acc[r][0] = ffma2(dy, wv1.x, acc[r][0]);
                acc[r][1] = ffma2(dy, wv1.y, acc[r][1]);
            }
        }
        #pragma unroll
        for (int r = 0; r < 8; r++) {
            int gr = base + w * 8 + r;
            if (gr < N) {
                float dsc = g_dis[gr];
                float2 p0 = unpack2(acc[r][0]), p1 = unpack2(acc[r][1]);
                float4 o = make_float4(p0.x * dsc, p0.y * dsc, p1.x * dsc, p1.y * dsc);
                *(float4*)&g_h1s[(size_t)gr * 128 + lane * 4] = o;
            }
        }
    }
}

// ---------------- k5: down-scan (side stream) ------------------------------------
__global__ void scan_down_kernel(int N) {
    __shared__ int sh[1024];
    __shared__ int base_off;
    int tid = threadIdx.x;
    if (tid < 32) {
        int v = 0;
        for (int j = tid; j < blockIdx.x; j += 32) v += g_bsum[j];
        #pragma unroll
        for (int o = 16; o; o >>= 1) v += __shfl_down_sync(0xffffffffu, v, o);
        if (tid == 0) base_off = v;
    }
    int i = blockIdx.x * 1024 + tid;
    int c = (i < N) ? g_cnt[i] : 0;
    sh[tid] = c; __syncthreads();
    for (int s = 1; s < 1024; s <<= 1) {
        int t = (tid >= s) ? sh[tid - s] : 0;
        __syncthreads();
        sh[tid] += t;
        __syncthreads();
    }
    if (i < N) {
        int st = base_off + sh[tid] - c;
        g_start[i] = st;
        g_cursor[i] = st;
    }
}

// ---------------- k6: CSR fill (side stream) --------------------------------------
__global__ void fill_kernel(const int* __restrict__ ei, int E) {
    int e = blockIdx.x * blockDim.x + threadIdx.x;
    if (e >= E) return;
    int src = ei[e], dst = ei[E + e];
    int p = atomicAdd(&g_cursor[dst], 1);
    g_csr[p] = src;
}

// ---------------- k7: agg1 -> z1 = relu(bn(dis*(sum h1s + self))) -----------------
__global__ __launch_bounds__(256) void agg1_kernel(int N) {
    int gw = blockIdx.x * 8 + (threadIdx.x >> 5);
    int lane = threadIdx.x & 31;
    if (gw >= N) return;
    const float* base = g_h1s;
    float4 a0 = *(const float4*)&base[(size_t)gw * 128 + lane * 4];  // self
    float4 a1 = make_float4(0.f, 0.f, 0.f, 0.f);
    float4 a2 = make_float4(0.f, 0.f, 0.f, 0.f);
    float4 a3 = make_float4(0.f, 0.f, 0.f, 0.f);
    int s = g_start[gw];
    int e = s + g_cnt[gw];
    int j = s;
    for (; j + 3 < e; j += 4) {
        int i0 = g_csr[j], i1 = g_csr[j + 1], i2 = g_csr[j + 2], i3 = g_csr[j + 3];
        float4 v0 = *(const float4*)&base[(size_t)i0 * 128 + lane * 4];
        float4 v1 = *(const float4*)&base[(size_t)i1 * 128 + lane * 4];
        float4 v2 = *(const float4*)&base[(size_t)i2 * 128 + lane * 4];
        float4 v3 = *(const float4*)&base[(size_t)i3 * 128 + lane * 4];
        add4(a0, v0); add4(a1, v1); add4(a2, v2); add4(a3, v3);
    }
    for (; j < e; j++) {
        float4 v0 = *(const float4*)&base[(size_t)g_csr[j] * 128 + lane * 4];
        add4(a0, v0);
    }
    a0.x += a1.x + a2.x + a3.x;
    a0.y += a1.y + a2.y + a3.y;
    a0.z += a1.z + a2.z + a3.z;
    a0.w += a1.w + a2.w + a3.w;
    float d = g_dis[gw];
    float4 sc = *(const float4*)&g_scale1[lane * 4];
    float4 sh = *(const float4*)&g_shift1[lane * 4];
    float4 z;
    z.x = fmaxf(fmaf(a0.x * d, sc.x, sh.x), 0.f);
    z.y = fmaxf(fmaf(a0.y * d, sc.y, sh.y), 0.f);
    z.z = fmaxf(fmaf(a0.z * d, sc.z, sh.z), 0.f);
    z.w = fmaxf(fmaf(a0.w * d, sc.w, sh.w), 0.f);
    *(float4*)&g_z1[(size_t)gw * 128 + lane * 4] = z;
}

// ---------------- k8: persistent GEMM2 h2s = (z1@W2)*dis ---------------------------
// grid 444 (3/SM, 64KB); plain activation storage; thread = 4 rows x 4 cols.
__global__ __launch_bounds__(256) void gemm2_kernel(const float* __restrict__ W,
                                                    int N, int ntiles) {
    float* Ws = (float*)smem_raw;                              // [128][64] = 32KB
    float* zs = (float*)(smem_raw + 32768);                    // [64][128] = 32KB
    float2 (*zs2)[64] = (float2(*)[64])zs;
    const int tid = threadIdx.x;
    for (int i = tid; i < 128 * 64; i += 256) Ws[i] = W[i];
    const int c4 = tid & 15;     // cols c4*4..+3
    const int rg = tid >> 4;     // rows rg*4..+3
    for (int tile = blockIdx.x; tile < ntiles; tile += gridDim.x) {
        const int base = tile * 64;
        __syncthreads();
        for (int i = tid; i < 2048; i += 256) {    // 64 rows x 32 float4
            int r = i >> 5, k4 = i & 31;
            int gr = base + r;
            float4 v = make_float4(0.f, 0.f, 0.f, 0.f);
            if (gr < N) v = *(const float4*)&g_z1[(size_t)gr * 128 + k4 * 4];
            *(float4*)&zs[r * 128 + k4 * 4] = v;
        }
        __syncthreads();
        ull acc[4][2];
        #pragma unroll
        for (int r = 0; r < 4; r++) { acc[r][0] = 0ull; acc[r][1] = 0ull; }
        #pragma unroll 4
        for (int kk = 0; kk < 64; kk++) {
            ulonglong2 wv0 = *(const ulonglong2*)&Ws[(2 * kk + 0) * 64 + c4 * 4];
            ulonglong2 wv1 = *(const ulonglong2*)&Ws[(2 * kk + 1) * 64 + c4 * 4];
            #pragma unroll
            for (int r = 0; r < 4; r++) {
                float2 d = zs2[rg * 4 + r][kk];
                ull dx = pack2(d.x, d.x);
                ull dy = pack2(d.y, d.y);
                acc[r][0] = ffma2(dx, wv0.x, acc[r][0]);
                acc[r][1] = ffma2(dx, wv0.y, acc[r][1]);
                acc[r][0] = ffma2(dy, wv1.x, acc[r][0]);
                acc[r][1] = ffma2(dy, wv1.y, acc[r][1]);
            }
        }
        #pragma unroll
        for (int r = 0; r < 4; r++) {
            int gr = base + rg * 4 + r;
            if (gr < N) {
                float dsc = g_dis[gr];
                float2 p0 = unpack2(acc[r][0]), p1 = unpack2(acc[r][1]);
                float4 o = make_float4(p0.x * dsc, p0.y * dsc, p1.x * dsc, p1.y * dsc);
                *(float4*)&g_h2s[(size_t)gr * 64 + c4 * 4] = o;
            }
        }
    }
}

// ---------------- k9: agg2+bn+relu+W3 -> h3s ---------------------------------------
__global__ __launch_bounds__(256) void agg23_kernel(const float* __restrict__ W3, int N) {
    __shared__ float W3s[128];
    int tid = threadIdx.x;
    if (tid < 128) W3s[tid] = W3[tid];
    __syncthreads();
    int gw = blockIdx.x * 8 + (tid >> 5);
    int lane = tid & 31;
    if (gw >= N) return;
    const float* base = g_h2s;
    float2 a0 = *(const float2*)&base[(size_t)gw * 64 + lane * 2];  // self
    float2 a1 = make_float2(0.f, 0.f);
    float2 a2 = make_float2(0.f, 0.f);
    float2 a3 = make_float2(0.f, 0.f);
    int s = g_start[gw];
    int e = s + g_cnt[gw];
    int j = s;
    for (; j + 3 < e; j += 4) {
        int i0 = g_csr[j], i1 = g_csr[j + 1], i2 = g_csr[j + 2], i3 = g_csr[j + 3];
        float2 v0 = *(const float2*)&base[(size_t)i0 * 64 + lane * 2];
        float2 v1 = *(const float2*)&base[(size_t)i1 * 64 + lane * 2];
        float2 v2 = *(const float2*)&base[(size_t)i2 * 64 + lane * 2];
        float2 v3 = *(const float2*)&base[(size_t)i3 * 64 + lane * 2];
        a0.x += v0.x; a0.y += v0.y;
        a1.x += v1.x; a1.y += v1.y;
        a2.x += v2.x; a2.y += v2.y;
        a3.x += v3.x; a3.y += v3.y;
    }
    for (; j < e; j++) {
        float2 v0 = *(const float2*)&base[(size_t)g_csr[j] * 64 + lane * 2];
        a0.x += v0.x; a0.y += v0.y;
    }
    a0.x += a1.x + a2.x + a3.x;
    a0.y += a1.y + a2.y + a3.y;
    float d = g_dis[gw];
    float2 sc = *(const float2*)&g_scale2[lane * 2];
    float2 sh = *(const float2*)&g_shift2[lane * 2];
    float zx = fmaxf(fmaf(a0.x * d, sc.x, sh.x), 0.f);
    float zy = fmaxf(fmaf(a0.y * d, sc.y, sh.y), 0.f);
    float s0 = fmaf(zx, W3s[4 * lane + 0], zy * W3s[4 * lane + 2]);
    float s1 = fmaf(zx, W3s[4 * lane + 1], zy * W3s[4 * lane + 3]);
    #pragma unroll
    for (int off = 16; off; off >>= 1) {
        s0 += __shfl_down_sync(0xffffffffu, s0, off);
        s1 += __shfl_down_sync(0xffffffffu, s1, off);
    }
    if (lane == 0) g_h3s[gw] = make_float2(s0 * d, s1 * d);
}

// ---------------- k10: agg3 -> out ---------------------------------------------------
__global__ void agg3_kernel(const float* __restrict__ b3, int N, float2* __restrict__ out) {
    int i = blockIdx.x * blockDim.x + threadIdx.x;
    if (i >= N) return;
    float2 acc = g_h3s[i];
    float2 a1 = make_float2(0.f, 0.f);
    float2 a2 = make_float2(0.f, 0.f);
    float2 a3 = make_float2(0.f, 0.f);
    int s = g_start[i];
    int e = s + g_cnt[i];
    int j = s;
    for (; j + 3 < e; j += 4) {
        float2 v0 = g_h3s[g_csr[j]];
        float2 v1 = g_h3s[g_csr[j + 1]];
        float2 v2 = g_h3s[g_csr[j + 2]];
        float2 v3 = g_h3s[g_csr[j + 3]];
        acc.x += v0.x; acc.y += v0.y;
        a1.x += v1.x; a1.y += v1.y;
        a2.x += v2.x; a2.y += v2.y;
        a3.x += v3.x; a3.y += v3.y;
    }
    for (; j < e; j++) {
        float2 v = g_h3s[g_csr[j]];
        acc.x += v.x; acc.y += v.y;
    }
    acc.x += a1.x + a2.x + a3.x;
    acc.y += a1.y + a2.y + a3.y;
    float d = g_dis[i];
    out[i] = make_float2(fmaf(acc.x, d, b3[0]), fmaf(acc.y, d, b3[1]));
}

// ---------------- launch --------------------------------------------------------------
extern "C" void kernel_launch(void* const* d_in, const int* in_sizes, int n_in,
                              void* d_out, int out_size) {
    const float* x   = (const float*)d_in[0];
    const int*   ei  = (const int*)d_in[1];
    const float* W1  = (const float*)d_in[2];
    const float* b1  = (const float*)d_in[3];
    const float* g1  = (const float*)d_in[4];
    const float* be1 = (const float*)d_in[5];
    const float* m1  = (const float*)d_in[6];
    const float* v1  = (const float*)d_in[7];
    const float* W2  = (const float*)d_in[8];
    const float* b2  = (const float*)d_in[9];
    const float* g2  = (const float*)d_in[10];
    const float* be2 = (const float*)d_in[11];
    const float* m2  = (const float*)d_in[12];
    const float* v2  = (const float*)d_in[13];
    const float* W3  = (const float*)d_in[14];
    const float* b3  = (const float*)d_in[15];

    const int N = in_sizes[0] / 64;
    const int E = in_sizes[1] / 2;
    float2* out = (float2*)d_out;
    const int NB = (N + 1023) / 1024;
    const int NT64 = (N + 63) / 64;

    static cudaStream_t s_side = nullptr;
    static cudaEvent_t ev_fork = nullptr, ev_join = nullptr;
    if (!s_side) {  // first call is the uncaptured correctness run
        cudaStreamCreateWithFlags(&s_side, cudaStreamNonBlocking);
        cudaEventCreateWithFlags(&ev_fork, cudaEventDisableTiming);
        cudaEventCreateWithFlags(&ev_join, cudaEventDisableTiming);
        cudaFuncSetAttribute(gemm1_kernel, cudaFuncAttributeMaxDynamicSharedMemorySize, 49152);
        cudaFuncSetAttribute(gemm2_kernel, cudaFuncAttributeMaxDynamicSharedMemorySize, 65536);
    }

    prep_zero_kernel<<<(N + 255) / 256, 256>>>(b1, g1, be1, m1, v1, b2, g2, be2, m2, v2, N);
    hist_kernel<<<(E + 255) / 256, 256>>>(ei, E);
    scan_part_kernel<<<NB, 1024>>>(N);

    // fork: CSR finalize on side stream, GEMM1 on main stream
    cudaEventRecord(ev_fork, 0);
    cudaStreamWaitEvent(s_side, ev_fork, 0);

    gemm1_kernel<<<592, 256, 49152>>>(x, W1, N, NT64);   // 4th kernel: profiled

    scan_down_kernel<<<NB, 1024, 0, s_side>>>(N);
    fill_kernel<<<(E + 255) / 256, 256, 0, s_side>>>(ei, E);
    cudaEventRecord(ev_join, s_side);
    cudaStreamWaitEvent(0, ev_join, 0);

    agg1_kernel<<<(N + 7) / 8, 256>>>(N);
    gemm2_kernel<<<444, 256, 65536>>>(W2, N, NT64);
    agg23_kernel<<<(N + 7) / 8, 256>>>(W3, N);
    agg3_kernel<<<(N + 255) / 256, 256>>>(b3, N, out);
}

// round 11
// speedup vs baseline: 1.0079x; 1.0079x over previous
#include <cuda_runtime.h>
#include <cstdint>

#define MAXN 100000
#define MAXE 800000
#define BN_EPS 1e-5f

typedef unsigned long long ull;

// ---------------- scratch ----------------------------------------------------
__device__ int   g_cnt[MAXN];
__device__ int   g_start[MAXN];
__device__ int   g_cursor[MAXN];
__device__ int   g_csr[MAXE];
__device__ int   g_bsum[128];
__device__ float g_dis[MAXN];            // rsqrt(deg+1)
__device__ float g_h1s[MAXN * 128];      // (x@W1)*dis
__device__ float g_z1[MAXN * 128];       // relu(bn(agg1))
__device__ float g_h2s[MAXN * 64];       // (z1@W2)*dis
__device__ float2 g_h3s[MAXN];           // (z2@W3)*dis
__device__ float g_scale1[128], g_shift1[128];
__device__ float g_scale2[64],  g_shift2[64];

// ---------------- f32x2 helpers ----------------------------------------------
__device__ __forceinline__ ull ffma2(ull a, ull b, ull c) {
    ull d; asm("fma.rn.f32x2 %0, %1, %2, %3;" : "=l"(d) : "l"(a), "l"(b), "l"(c));
    return d;
}
__device__ __forceinline__ ull pack2(float x, float y) {
    ull d; asm("mov.b64 %0, {%1,%2};" : "=l"(d) : "f"(x), "f"(y)); return d;
}
__device__ __forceinline__ float2 unpack2(ull v) {
    float2 r; asm("mov.b64 {%0,%1}, %2;" : "=f"(r.x), "=f"(r.y) : "l"(v)); return r;
}
__device__ __forceinline__ void add4(float4& a, const float4& v) {
    a.x += v.x; a.y += v.y; a.z += v.z; a.w += v.w;
}

// ---------------- k1: prep BN params + zero cnt --------------------------------
__global__ void prep_zero_kernel(const float* __restrict__ b1, const float* __restrict__ g1,
                                 const float* __restrict__ be1, const float* __restrict__ m1,
                                 const float* __restrict__ v1,
                                 const float* __restrict__ b2, const float* __restrict__ g2,
                                 const float* __restrict__ be2, const float* __restrict__ m2,
                                 const float* __restrict__ v2, int N) {
    int i = blockIdx.x * blockDim.x + threadIdx.x;
    if (i < N) g_cnt[i] = 0;
    if (blockIdx.x == 0) {
        int t = threadIdx.x;
        if (t < 128) {
            float s = g1[t] * rsqrtf(v1[t] + BN_EPS);
            g_scale1[t] = s;
            g_shift1[t] = fmaf(b1[t] - m1[t], s, be1[t]);
        }
        if (t < 64) {
            float s = g2[t] * rsqrtf(v2[t] + BN_EPS);
            g_scale2[t] = s;
            g_shift2[t] = fmaf(b2[t] - m2[t], s, be2[t]);
        }
    }
}

// ---------------- k2: hist ------------------------------------------------------
__global__ void hist_kernel(const int* __restrict__ ei, int E) {
    int e = blockIdx.x * blockDim.x + threadIdx.x;
    if (e < E) atomicAdd(&g_cnt[ei[E + e]], 1);
}

// ---------------- k3: per-block sums + dis --------------------------------------
__global__ void scan_part_kernel(int N) {
    __shared__ int sh[1024];
    int i = blockIdx.x * 1024 + threadIdx.x;
    int c = (i < N) ? g_cnt[i] : 0;
    if (i < N) g_dis[i] = rsqrtf((float)c + 1.0f);
    sh[threadIdx.x] = c; __syncthreads();
    for (int s = 512; s > 0; s >>= 1) {
        if (threadIdx.x < s) sh[threadIdx.x] += sh[threadIdx.x + s];
        __syncthreads();
    }
    if (threadIdx.x == 0) g_bsum[blockIdx.x] = sh[0];
}

// ---------------- k4 (PROFILED SLOT): persistent GEMM1 h1s = (x@W1)*dis ---------
// grid 592 (4/SM, 48KB); activations stored plain (broadcast LDS.64 + reg dup).
// thread = 8 rows x 4 cols.
extern __shared__ char smem_raw[];
__global__ __launch_bounds__(256) void gemm1_kernel(const float* __restrict__ x,
                                                    const float* __restrict__ W,
                                                    int N, int ntiles) {
    float* Ws = (float*)smem_raw;                              // [64][128] = 32KB
    float* xs = (float*)(smem_raw + 32768);                    // [64][64]  = 16KB
    float2 (*xs2)[32] = (float2(*)[32])xs;
    const int tid = threadIdx.x;
    for (int i = tid; i < 64 * 128; i += 256) Ws[i] = W[i];
    const int lane = tid & 31;   // cols lane*4..+3
    const int w    = tid >> 5;   // rows w*8..+7
    for (int tile = blockIdx.x; tile < ntiles; tile += gridDim.x) {
        const int base = tile * 64;
        __syncthreads();   // orders W-store (first iter) / prev compute vs tile load
        for (int i = tid; i < 1024; i += 256) {      // 64 rows x 16 float4
            int r = i >> 4, k4 = i & 15;
            int gr = base + r;
            float4 v = make_float4(0.f, 0.f, 0.f, 0.f);
            if (gr < N) v = *(const float4*)&x[(size_t)gr * 64 + k4 * 4];
            *(float4*)&xs[r * 64 + k4 * 4] = v;
        }
        __syncthreads();
        ull acc[8][2];
        #pragma unroll
        for (int r = 0; r < 8; r++) { acc[r][0] = 0ull; acc[r][1] = 0ull; }
        #pragma unroll 4
        for (int kk = 0; kk < 32; kk++) {
            ulonglong2 wv0 = *(const ulonglong2*)&Ws[(2 * kk + 0) * 128 + lane * 4];
            ulonglong2 wv1 = *(const ulonglong2*)&Ws[(2 * kk + 1) * 128 + lane * 4];
            #pragma unroll
            for (int r = 0; r < 8; r++) {
                float2 d = xs2[w * 8 + r][kk];
                ull dx = pack2(d.x, d.x);
                ull dy = pack2(d.y, d.y);
                acc[r][0] = ffma2(dx, wv0.x, acc[r][0]);
                acc[r][1] = ffma2(dx, wv0.y, acc[r][1]);
                acc[r][0] = ffma2(dy, wv1.x, acc[r][0]);
                acc[r][1] = ffma2(dy, wv1.y, acc[r][1]);
            }
        }
        #pragma unroll
        for (int r = 0; r < 8; r++) {
            int gr = base + w * 8 + r;
            if (gr < N) {
                float dsc = g_dis[gr];
                float2 p0 = unpack2(acc[r][0]), p1 = unpack2(acc[r][1]);
                float4 o = make_float4(p0.x * dsc, p0.y * dsc, p1.x * dsc, p1.y * dsc);
                *(float4*)&g_h1s[(size_t)gr * 128 + lane * 4] = o;
            }
        }
    }
}

// ---------------- k5: down-scan (side stream) ------------------------------------
__global__ void scan_down_kernel(int N) {
    __shared__ int sh[1024];
    __shared__ int base_off;
    int tid = threadIdx.x;
    if (tid < 32) {
        int v = 0;
        for (int j = tid; j < blockIdx.x; j += 32) v += g_bsum[j];
        #pragma unroll
        for (int o = 16; o; o >>= 1) v += __shfl_down_sync(0xffffffffu, v, o);
        if (tid == 0) base_off = v;
    }
    int i = blockIdx.x * 1024 + tid;
    int c = (i < N) ? g_cnt[i] : 0;
    sh[tid] = c; __syncthreads();
    for (int s = 1; s < 1024; s <<= 1) {
        int t = (tid >= s) ? sh[tid - s] : 0;
        __syncthreads();
        sh[tid] += t;
        __syncthreads();
    }
    if (i < N) {
        int st = base_off + sh[tid] - c;
        g_start[i] = st;
        g_cursor[i] = st;
    }
}

// ---------------- k6: CSR fill (side stream) --------------------------------------
__global__ void fill_kernel(const int* __restrict__ ei, int E) {
    int e = blockIdx.x * blockDim.x + threadIdx.x;
    if (e >= E) return;
    int src = ei[e], dst = ei[E + e];
    int p = atomicAdd(&g_cursor[dst], 1);
    g_csr[p] = src;
}

// ---------------- k7: agg1 -> z1 = relu(bn(dis*(sum h1s + self))) -----------------
__global__ __launch_bounds__(256) void agg1_kernel(int N) {
    int gw = blockIdx.x * 8 + (threadIdx.x >> 5);
    int lane = threadIdx.x & 31;
    if (gw >= N) return;
    const float* base = g_h1s;
    float4 a0 = *(const float4*)&base[(size_t)gw * 128 + lane * 4];  // self
    float4 a1 = make_float4(0.f, 0.f, 0.f, 0.f);
    float4 a2 = make_float4(0.f, 0.f, 0.f, 0.f);
    float4 a3 = make_float4(0.f, 0.f, 0.f, 0.f);
    int s = g_start[gw];
    int e = s + g_cnt[gw];
    int j = s;
    for (; j + 3 < e; j += 4) {
        int i0 = g_csr[j], i1 = g_csr[j + 1], i2 = g_csr[j + 2], i3 = g_csr[j + 3];
        float4 v0 = *(const float4*)&base[(size_t)i0 * 128 + lane * 4];
        float4 v1 = *(const float4*)&base[(size_t)i1 * 128 + lane * 4];
        float4 v2 = *(const float4*)&base[(size_t)i2 * 128 + lane * 4];
        float4 v3 = *(const float4*)&base[(size_t)i3 * 128 + lane * 4];
        add4(a0, v0); add4(a1, v1); add4(a2, v2); add4(a3, v3);
    }
    for (; j < e; j++) {
        float4 v0 = *(const float4*)&base[(size_t)g_csr[j] * 128 + lane * 4];
        add4(a0, v0);
    }
    a0.x += a1.x + a2.x + a3.x;
    a0.y += a1.y + a2.y + a3.y;
    a0.z += a1.z + a2.z + a3.z;
    a0.w += a1.w + a2.w + a3.w;
    float d = g_dis[gw];
    float4 sc = *(const float4*)&g_scale1[lane * 4];
    float4 sh = *(const float4*)&g_shift1[lane * 4];
    float4 z;
    z.x = fmaxf(fmaf(a0.x * d, sc.x, sh.x), 0.f);
    z.y = fmaxf(fmaf(a0.y * d, sc.y, sh.y), 0.f);
    z.z = fmaxf(fmaf(a0.z * d, sc.z, sh.z), 0.f);
    z.w = fmaxf(fmaf(a0.w * d, sc.w, sh.w), 0.f);
    *(float4*)&g_z1[(size_t)gw * 128 + lane * 4] = z;
}

// ---------------- k8: persistent GEMM2 h2s = (z1@W2)*dis ---------------------------
// grid 444 (3/SM, 64KB); plain activation storage; thread = 4 rows x 4 cols.
__global__ __launch_bounds__(256) void gemm2_kernel(const float* __restrict__ W,
                                                    int N, int ntiles) {
    float* Ws = (float*)smem_raw;                              // [128][64] = 32KB
    float* zs = (float*)(smem_raw + 32768);                    // [64][128] = 32KB
    float2 (*zs2)[64] = (float2(*)[64])zs;
    const int tid = threadIdx.x;
    for (int i = tid; i < 128 * 64; i += 256) Ws[i] = W[i];
    const int c4 = tid & 15;     // cols c4*4..+3
    const int rg = tid >> 4;     // rows rg*4..+3
    for (int tile = blockIdx.x; tile < ntiles; tile += gridDim.x) {
        const int base = tile * 64;
        __syncthreads();
        for (int i = tid; i < 2048; i += 256) {    // 64 rows x 32 float4
            int r = i >> 5, k4 = i & 31;
            int gr = base + r;
            float4 v = make_float4(0.f, 0.f, 0.f, 0.f);
            if (gr < N) v = *(const float4*)&g_z1[(size_t)gr * 128 + k4 * 4];
            *(float4*)&zs[r * 128 + k4 * 4] = v;
        }
        __syncthreads();
        ull acc[4][2];
        #pragma unroll
        for (int r = 0; r < 4; r++) { acc[r][0] = 0ull; acc[r][1] = 0ull; }
        #pragma unroll 4
        for (int kk = 0; kk < 64; kk++) {
            ulonglong2 wv0 = *(const ulonglong2*)&Ws[(2 * kk + 0) * 64 + c4 * 4];
            ulonglong2 wv1 = *(const ulonglong2*)&Ws[(2 * kk + 1) * 64 + c4 * 4];
            #pragma unroll
            for (int r = 0; r < 4; r++) {
                float2 d = zs2[rg * 4 + r][kk];
                ull dx = pack2(d.x, d.x);
                ull dy = pack2(d.y, d.y);
                acc[r][0] = ffma2(dx, wv0.x, acc[r][0]);
                acc[r][1] = ffma2(dx, wv0.y, acc[r][1]);
                acc[r][0] = ffma2(dy, wv1.x, acc[r][0]);
                acc[r][1] = ffma2(dy, wv1.y, acc[r][1]);
            }
        }
        #pragma unroll
        for (int r = 0; r < 4; r++) {
            int gr = base + rg * 4 + r;
            if (gr < N) {
                float dsc = g_dis[gr];
                float2 p0 = unpack2(acc[r][0]), p1 = unpack2(acc[r][1]);
                float4 o = make_float4(p0.x * dsc, p0.y * dsc, p1.x * dsc, p1.y * dsc);
                *(float4*)&g_h2s[(size_t)gr * 64 + c4 * 4] = o;
            }
        }
    }
}

// ---------------- k9: agg2+bn+relu+W3 -> h3s ---------------------------------------
__global__ __launch_bounds__(256) void agg23_kernel(const float* __restrict__ W3, int N) {
    __shared__ float W3s[128];
    int tid = threadIdx.x;
    if (tid < 128) W3s[tid] = W3[tid];
    __syncthreads();
    int gw = blockIdx.x * 8 + (tid >> 5);
    int lane = tid & 31;
    if (gw >= N) return;
    const float* base = g_h2s;
    float2 a0 = *(const float2*)&base[(size_t)gw * 64 + lane * 2];  // self
    float2 a1 = make_float2(0.f, 0.f);
    float2 a2 = make_float2(0.f, 0.f);
    float2 a3 = make_float2(0.f, 0.f);
    int s = g_start[gw];
    int e = s + g_cnt[gw];
    int j = s;
    for (; j + 3 < e; j += 4) {
        int i0 = g_csr[j], i1 = g_csr[j + 1], i2 = g_csr[j + 2], i3 = g_csr[j + 3];
        float2 v0 = *(const float2*)&base[(size_t)i0 * 64 + lane * 2];
        float2 v1 = *(const float2*)&base[(size_t)i1 * 64 + lane * 2];
        float2 v2 = *(const float2*)&base[(size_t)i2 * 64 + lane * 2];
        float2 v3 = *(const float2*)&base[(size_t)i3 * 64 + lane * 2];
        a0.x += v0.x; a0.y += v0.y;
        a1.x += v1.x; a1.y += v1.y;
        a2.x += v2.x; a2.y += v2.y;
        a3.x += v3.x; a3.y += v3.y;
    }
    for (; j < e; j++) {
        float2 v0 = *(const float2*)&base[(size_t)g_csr[j] * 64 + lane * 2];
        a0.x += v0.x; a0.y += v0.y;
    }
    a0.x += a1.x + a2.x + a3.x;
    a0.y += a1.y + a2.y + a3.y;
    float d = g_dis[gw];
    float2 sc = *(const float2*)&g_scale2[lane * 2];
    float2 sh = *(const float2*)&g_shift2[lane * 2];
    float zx = fmaxf(fmaf(a0.x * d, sc.x, sh.x), 0.f);
    float zy = fmaxf(fmaf(a0.y * d, sc.y, sh.y), 0.f);
    float s0 = fmaf(zx, W3s[4 * lane + 0], zy * W3s[4 * lane + 2]);
    float s1 = fmaf(zx, W3s[4 * lane + 1], zy * W3s[4 * lane + 3]);
    #pragma unroll
    for (int off = 16; off; off >>= 1) {
        s0 += __shfl_down_sync(0xffffffffu, s0, off);
        s1 += __shfl_down_sync(0xffffffffu, s1, off);
    }
    if (lane == 0) g_h3s[gw] = make_float2(s0 * d, s1 * d);
}

// ---------------- k10: agg3 -> out ---------------------------------------------------
__global__ void agg3_kernel(const float* __restrict__ b3, int N, float2* __restrict__ out) {
    int i = blockIdx.x * blockDim.x + threadIdx.x;
    if (i >= N) return;
    float2 acc = g_h3s[i];
    float2 a1 = make_float2(0.f, 0.f);
    float2 a2 = make_float2(0.f, 0.f);
    float2 a3 = make_float2(0.f, 0.f);
    int s = g_start[i];
    int e = s + g_cnt[i];
    int j = s;
    for (; j + 3 < e; j += 4) {
        float2 v0 = g_h3s[g_csr[j]];
        float2 v1 = g_h3s[g_csr[j + 1]];
        float2 v2 = g_h3s[g_csr[j + 2]];
        float2 v3 = g_h3s[g_csr[j + 3]];
        acc.x += v0.x; acc.y += v0.y;
        a1.x += v1.x; a1.y += v1.y;
        a2.x += v2.x; a2.y += v2.y;
        a3.x += v3.x; a3.y += v3.y;
    }
    for (; j < e; j++) {
        float2 v = g_h3s[g_csr[j]];
        acc.x += v.x; acc.y += v.y;
    }
    acc.x += a1.x + a2.x + a3.x;
    acc.y += a1.y + a2.y + a3.y;
    float d = g_dis[i];
    out[i] = make_float2(fmaf(acc.x, d, b3[0]), fmaf(acc.y, d, b3[1]));
}

// ---------------- launch --------------------------------------------------------------
extern "C" void kernel_launch(void* const* d_in, const int* in_sizes, int n_in,
                              void* d_out, int out_size) {
    const float* x   = (const float*)d_in[0];
    const int*   ei  = (const int*)d_in[1];
    const float* W1  = (const float*)d_in[2];
    const float* b1  = (const float*)d_in[3];
    const float* g1  = (const float*)d_in[4];
    const float* be1 = (const float*)d_in[5];
    const float* m1  = (const float*)d_in[6];
    const float* v1  = (const float*)d_in[7];
    const float* W2  = (const float*)d_in[8];
    const float* b2  = (const float*)d_in[9];
    const float* g2  = (const float*)d_in[10];
    const float* be2 = (const float*)d_in[11];
    const float* m2  = (const float*)d_in[12];
    const float* v2  = (const float*)d_in[13];
    const float* W3  = (const float*)d_in[14];
    const float* b3  = (const float*)d_in[15];

    const int N = in_sizes[0] / 64;
    const int E = in_sizes[1] / 2;
    float2* out = (float2*)d_out;
    const int NB = (N + 1023) / 1024;
    const int NT64 = (N + 63) / 64;

    static cudaStream_t s_side = nullptr;
    static cudaEvent_t ev_fork = nullptr, ev_join = nullptr;
    if (!s_side) {  // first call is the uncaptured correctness run
        cudaStreamCreateWithFlags(&s_side, cudaStreamNonBlocking);
        cudaEventCreateWithFlags(&ev_fork, cudaEventDisableTiming);
        cudaEventCreateWithFlags(&ev_join, cudaEventDisableTiming);
        cudaFuncSetAttribute(gemm1_kernel, cudaFuncAttributeMaxDynamicSharedMemorySize, 49152);
        cudaFuncSetAttribute(gemm2_kernel, cudaFuncAttributeMaxDynamicSharedMemorySize, 65536);
    }

    prep_zero_kernel<<<(N + 255) / 256, 256>>>(b1, g1, be1, m1, v1, b2, g2, be2, m2, v2, N);
    hist_kernel<<<(E + 255) / 256, 256>>>(ei, E);
    scan_part_kernel<<<NB, 1024>>>(N);

    // fork: CSR finalize on side stream, GEMM1 on main stream
    cudaEventRecord(ev_fork, 0);
    cudaStreamWaitEvent(s_side, ev_fork, 0);

    gemm1_kernel<<<592, 256, 49152>>>(x, W1, N, NT64);   // 4th kernel: profiled

    scan_down_kernel<<<NB, 1024, 0, s_side>>>(N);
    fill_kernel<<<(E + 255) / 256, 256, 0, s_side>>>(ei, E);
    cudaEventRecord(ev_join, s_side);
    cudaStreamWaitEvent(0, ev_join, 0);

    agg1_kernel<<<(N + 7) / 8, 256>>>(N);
    gemm2_kernel<<<444, 256, 65536>>>(W2, N, NT64);
    agg23_kernel<<<(N + 7) / 8, 256>>>(W3, N);
    agg3_kernel<<<(N + 255) / 256, 256>>>(b3, N, out);
}